// round 15
// baseline (speedup 1.0000x reference)
#include <cuda_runtime.h>
#include <cuda_fp16.h>
#include <cstdint>

// Problem constants
#define NB 4
#define NS 1024
#define ND 1024
#define NH 16
#define DH 64
#define NM (NB * NS)   // 4096 rows

// Scratch (allocation-free rule: __device__ globals)
__device__ __half g_xn[NM * ND];       // layernormed x, fp16, [4096][1024]
__device__ __half g_wt[3 * ND * ND];   // W^T fp16, [z][n][k]
__device__ __half g_qh[NM * ND];       // [B*H][S][64], PRE-SCALED by 0.125
__device__ __half g_kh[NM * ND];
__device__ __half g_vh[NM * ND];

// ---------------------------------------------------------------------------
// helpers
// ---------------------------------------------------------------------------
__device__ __forceinline__ void mma_f16(float c[4],
                                        uint32_t a0, uint32_t a1, uint32_t a2, uint32_t a3,
                                        uint32_t b0, uint32_t b1) {
    asm volatile(
        "mma.sync.aligned.m16n8k16.row.col.f32.f16.f16.f32 "
        "{%0,%1,%2,%3},{%4,%5,%6,%7},{%8,%9},{%0,%1,%2,%3};\n"
        : "+f"(c[0]), "+f"(c[1]), "+f"(c[2]), "+f"(c[3])
        : "r"(a0), "r"(a1), "r"(a2), "r"(a3), "r"(b0), "r"(b1));
}

__device__ __forceinline__ void ldsm4(uint32_t& r0, uint32_t& r1, uint32_t& r2, uint32_t& r3,
                                      uint32_t addr) {
    asm volatile("ldmatrix.sync.aligned.m8n8.x4.shared.b16 {%0,%1,%2,%3}, [%4];"
                 : "=r"(r0), "=r"(r1), "=r"(r2), "=r"(r3) : "r"(addr));
}
__device__ __forceinline__ void ldsm2(uint32_t& r0, uint32_t& r1, uint32_t addr) {
    asm volatile("ldmatrix.sync.aligned.m8n8.x2.shared.b16 {%0,%1}, [%2];"
                 : "=r"(r0), "=r"(r1) : "r"(addr));
}
__device__ __forceinline__ uint32_t smem_u32(const void* p) {
    return (uint32_t)__cvta_generic_to_shared(p);
}

// ---------------------------------------------------------------------------
// Kernel 1: LayerNorm -> fp16. One block per row, 256 threads.
// ---------------------------------------------------------------------------
__global__ void __launch_bounds__(256)
ln_kernel(const float* __restrict__ x,
          const float* __restrict__ gamma,
          const float* __restrict__ beta) {
    int row = blockIdx.x;
    int tid = threadIdx.x;
    const float4* xr = reinterpret_cast<const float4*>(x + (size_t)row * ND);
    float4 v = xr[tid];

    float s1 = v.x + v.y + v.z + v.w;
    float s2 = v.x * v.x + v.y * v.y + v.z * v.z + v.w * v.w;

    __shared__ float red1[8];
    __shared__ float red2[8];
    #pragma unroll
    for (int o = 16; o; o >>= 1) {
        s1 += __shfl_xor_sync(0xffffffffu, s1, o);
        s2 += __shfl_xor_sync(0xffffffffu, s2, o);
    }
    if ((tid & 31) == 0) { red1[tid >> 5] = s1; red2[tid >> 5] = s2; }
    __syncthreads();
    if (tid == 0) {
        float t1 = 0.f, t2 = 0.f;
        #pragma unroll
        for (int i = 0; i < 8; i++) { t1 += red1[i]; t2 += red2[i]; }
        red1[0] = t1; red2[0] = t2;
    }
    __syncthreads();
    float mu = red1[0] * (1.0f / ND);
    float var = red2[0] * (1.0f / ND) - mu * mu;
    float rstd = rsqrtf(var + 1e-5f);

    const float4 g4 = reinterpret_cast<const float4*>(gamma)[tid];
    const float4 b4 = reinterpret_cast<const float4*>(beta)[tid];
    float o0 = (v.x - mu) * rstd * g4.x + b4.x;
    float o1 = (v.y - mu) * rstd * g4.y + b4.y;
    float o2 = (v.z - mu) * rstd * g4.z + b4.z;
    float o3 = (v.w - mu) * rstd * g4.w + b4.w;

    size_t off = (size_t)row * ND + tid * 4;
    *reinterpret_cast<__half2*>(g_xn + off)     = __floats2half2_rn(o0, o1);
    *reinterpret_cast<__half2*>(g_xn + off + 2) = __floats2half2_rn(o2, o3);
}

// ---------------------------------------------------------------------------
// Kernel 1b: W transpose -> fp16. Wt[n][k] = W[k][n].
// ---------------------------------------------------------------------------
__global__ void __launch_bounds__(256)
wt_kernel(const float* __restrict__ Wq, const float* __restrict__ Wk,
          const float* __restrict__ Wv) {
    __shared__ float t[32][33];
    int z = blockIdx.z;
    const float* W = (z == 0) ? Wq : (z == 1) ? Wk : Wv;
    __half* oh = g_wt + (size_t)z * ND * ND;

    int k0 = blockIdx.x << 5, n0 = blockIdx.y << 5;
    int tx = threadIdx.x & 31, ty = threadIdx.x >> 5;

    #pragma unroll
    for (int i = 0; i < 32; i += 8)
        t[ty + i][tx] = W[(size_t)(k0 + ty + i) * ND + n0 + tx];
    __syncthreads();
    #pragma unroll
    for (int i = 0; i < 32; i += 8) {
        int n = ty + i;
        oh[(size_t)(n0 + n) * ND + k0 + tx] = __float2half_rn(t[tx][n]);
    }
}

// ---------------------------------------------------------------------------
// Kernel 2: QKV projection GEMM, fp16 m16n8k16 (unchanged from R8).
// ---------------------------------------------------------------------------
#define PITCH 72

__global__ void __launch_bounds__(256)
qkv_gemm(const float* __restrict__ bq, const float* __restrict__ bk,
         const float* __restrict__ bv) {
    __shared__ __half As[128 * PITCH];
    __shared__ __half Bs[128 * PITCH];

    int z = blockIdx.z;
    const float* bias = (z == 0) ? bq : (z == 1) ? bk : bv;
    __half* outp      = (z == 0) ? g_qh : (z == 1) ? g_kh : g_vh;
    float osc = (z == 0) ? 0.125f : 1.0f;
    const __half* W = g_wt + (size_t)z * ND * ND;

    int tid  = threadIdx.x;
    int lane = tid & 31;
    int warp = tid >> 5;
    int m_base = (warp & 1) * 64;
    int n_base = (warp >> 1) * 32;
    int qrow = lane >> 2;
    int qcol = lane & 3;

    int m0 = blockIdx.y << 7;
    int n0 = blockIdx.x << 7;

    int a_row = (lane & 7) + ((lane >> 3) & 1) * 8;
    int a_kof = ((lane >> 4) & 1) * 8;
    int b_row = lane & 7;
    int b_kof = ((lane >> 3) & 1) * 8;

    uint32_t As_u = smem_u32(As);
    uint32_t Bs_u = smem_u32(Bs);

    float acc[4][4][4];
    #pragma unroll
    for (int mt = 0; mt < 4; mt++)
        #pragma unroll
        for (int nt = 0; nt < 4; nt++)
            #pragma unroll
            for (int r = 0; r < 4; r++) acc[mt][nt][r] = 0.f;

    int r = tid >> 3, u = tid & 7;
    const __half* agp = g_xn + (size_t)(m0 + r) * ND + u * 8;
    const __half* bgp = W + (size_t)(n0 + r) * ND + u * 8;

    uint4 av[4], bv4[4];
    #pragma unroll
    for (int i = 0; i < 4; i++) av[i]  = *(const uint4*)(agp + (size_t)(32 * i) * ND);
    #pragma unroll
    for (int i = 0; i < 4; i++) bv4[i] = *(const uint4*)(bgp + (size_t)(32 * i) * ND);

    for (int it = 0; it < 16; it++) {
        __syncthreads();
        #pragma unroll
        for (int i = 0; i < 4; i++)
            *(uint4*)&As[(r + 32 * i) * PITCH + u * 8] = av[i];
        #pragma unroll
        for (int i = 0; i < 4; i++)
            *(uint4*)&Bs[(r + 32 * i) * PITCH + u * 8] = bv4[i];
        __syncthreads();

        if (it + 1 < 16) {
            int kof = (it + 1) * 64;
            #pragma unroll
            for (int i = 0; i < 4; i++) av[i]  = *(const uint4*)(agp + (size_t)(32 * i) * ND + kof);
            #pragma unroll
            for (int i = 0; i < 4; i++) bv4[i] = *(const uint4*)(bgp + (size_t)(32 * i) * ND + kof);
        }

        #pragma unroll
        for (int ks = 0; ks < 4; ks++) {
            uint32_t af[4][4];
            #pragma unroll
            for (int mt = 0; mt < 4; mt++)
                ldsm4(af[mt][0], af[mt][1], af[mt][2], af[mt][3],
                      As_u + (uint32_t)(((m_base + mt * 16 + a_row) * PITCH + ks * 16 + a_kof) << 1));
            uint32_t bf[4][2];
            #pragma unroll
            for (int nt = 0; nt < 4; nt++)
                ldsm2(bf[nt][0], bf[nt][1],
                      Bs_u + (uint32_t)(((n_base + nt * 8 + b_row) * PITCH + ks * 16 + b_kof) << 1));
            #pragma unroll
            for (int mt = 0; mt < 4; mt++)
                #pragma unroll
                for (int nt = 0; nt < 4; nt++)
                    mma_f16(acc[mt][nt],
                            af[mt][0], af[mt][1], af[mt][2], af[mt][3],
                            bf[nt][0], bf[nt][1]);
        }
    }

    #pragma unroll
    for (int mt = 0; mt < 4; mt++) {
        #pragma unroll
        for (int nt = 0; nt < 4; nt++) {
            int col = n0 + n_base + nt * 8 + 2 * qcol;
            int h = col >> 6, d = col & 63;
            float bx = bias[col], by = bias[col + 1];
            #pragma unroll
            for (int half_ = 0; half_ < 2; half_++) {
                int row = m0 + m_base + mt * 16 + qrow + half_ * 8;
                int b_ = row >> 10, s = row & 1023;
                __half2 hv = __floats2half2_rn((acc[mt][nt][half_ * 2 + 0] + bx) * osc,
                                               (acc[mt][nt][half_ * 2 + 1] + by) * osc);
                *(__half2*)(outp + (size_t)(((b_ * NH + h) << 10) + s) * DH + d) = hv;
            }
        }
    }
}

// ---------------------------------------------------------------------------
// Kernel 3: attention, fp16 mma, register-resident P, 1 sync per chunk.
// 512 threads (16 warps, 4x4 grid). Each warp: rows m_base..+16, and for S
// the j-slice n_base..+16 of the chunk. PV uses the S C-fragment repacked as
// the A-fragment directly (bitwise same halves as Ps), accumulating a PARTIAL
// O over its j-slice across the FULL 64 dv; 4-way O reduction in the epilogue
// through the Ps smem region (freed after the attn write).
// K/V double-buffered -> single __syncthreads per chunk.
// ---------------------------------------------------------------------------
#define PPITCH 1048
#define KVBUF (64 * PITCH)                     // halves per K or V buffer
// smem: Qs 9216 | Ks[2] 18432 | Vs[2] 18432 | rsA 1024 | Ps 134144
#define ATTN_SMEM_B (9216 + 18432 + 18432 + 1024 + 64 * PPITCH * 2)  // 181248

__global__ void __launch_bounds__(512)
attn_kernel(const float* __restrict__ x,
            const int* __restrict__ kvlen,
            float* __restrict__ out_seq,
            float* __restrict__ out_attn) {
    extern __shared__ char smc[];
    __half* Qs  = (__half*)smc;                         // [64][72]
    __half* Ks  = (__half*)(smc + 9216);                // [2][64][72]
    __half* Vs  = (__half*)(smc + 9216 + 18432);        // [2][dv 64][72]
    float*  rsA = (float*)(smc + 46080);                // [4][64]
    __half* Ps  = (__half*)(smc + 47104);               // [64][PPITCH]
    float*  Obuf = (float*)(smc + 47104);               // overlays Ps (epilogue)

    int tid  = threadIdx.x;
    int lane = tid & 31;
    int warp = tid >> 5;                        // 0..15
    int m_base = (warp >> 2) << 4;              // 0,16,32,48
    int n_base = (warp & 3) << 4;               // j-slice base 0,16,32,48
    int qrow = lane >> 2;
    int qcol = lane & 3;

    int a_row = (lane & 7) + ((lane >> 3) & 1) * 8;
    int a_kof = ((lane >> 4) & 1) * 8;
    int b_row = lane & 7;
    int b_kof = ((lane >> 3) & 1) * 8;

    uint32_t Qs_u = smem_u32(Qs);
    uint32_t Ks_u = smem_u32(Ks);
    uint32_t Vs_u = smem_u32(Vs);

    int bh = blockIdx.y;
    int b_ = bh >> 4, h = bh & 15;
    int q0 = (15 - blockIdx.x) << 6;            // heavy blocks first
    int kv = kvlen[b_];

    // load Q tile: one uint4 per thread (64 rows x 8 groups = 512)
    {
        int r = tid >> 3, u = tid & 7;
        *(uint4*)&Qs[r * PITCH + u * 8] =
            *(const uint4*)(g_qh + (size_t)(bh * NS + q0 + r) * DH + u * 8);
    }
    if (tid < 256) rsA[tid] = 0.f;

    float acc_o[8][4];                          // PARTIAL O: full dv, own j-slice
    #pragma unroll
    for (int dvt = 0; dvt < 8; dvt++)
        #pragma unroll
        for (int r = 0; r < 4; r++) acc_o[dvt][r] = 0.f;

    int qg0 = q0 + m_base + qrow;
    int qg1 = qg0 + 8;

    int jend = min(q0 + 64, kv);
    int nch = (jend + 63) >> 6;

    const __half* kb = g_kh + (size_t)(bh * NS) * DH;
    const __half* vb = g_vh + (size_t)(bh * NS) * DH;
    int kr = tid >> 3, ku = tid & 7;            // K: row 0..63, group 0..7
    int vp = (tid & 255) >> 3, vu = tid & 7;    // V (tid<256): row-pair 0..31

    uint4 kreg, vreg0, vreg1;
    #define ATTN_PREFETCH(j0_)                                                   \
        do {                                                                     \
            kreg = *(const uint4*)(kb + (size_t)((j0_) + kr) * DH + ku * 8);     \
            if (tid < 256) {                                                     \
                vreg0 = *(const uint4*)(vb + (size_t)((j0_) + 2 * vp) * DH + vu * 8);     \
                vreg1 = *(const uint4*)(vb + (size_t)((j0_) + 2 * vp + 1) * DH + vu * 8); \
            }                                                                    \
        } while (0)

    #define STORE_KV(buf_)                                                       \
        do {                                                                     \
            __half* ksb = Ks + (buf_) * KVBUF;                                   \
            __half* vsb = Vs + (buf_) * KVBUF;                                   \
            *(uint4*)&ksb[kr * PITCH + ku * 8] = kreg;                           \
            if (tid < 256) {                                                     \
                const uint32_t* pa_ = (const uint32_t*)&vreg0;                   \
                const uint32_t* pb_ = (const uint32_t*)&vreg1;                   \
                _Pragma("unroll")                                                \
                for (int i_ = 0; i_ < 4; i_++) {                                 \
                    uint32_t lo_ = __byte_perm(pa_[i_], pb_[i_], 0x5410);        \
                    uint32_t hi_ = __byte_perm(pa_[i_], pb_[i_], 0x7632);        \
                    int dv_ = vu * 8 + 2 * i_;                                   \
                    *(uint32_t*)&vsb[dv_ * PITCH + 2 * vp]       = lo_;          \
                    *(uint32_t*)&vsb[(dv_ + 1) * PITCH + 2 * vp] = hi_;          \
                }                                                                \
            }                                                                    \
        } while (0)

    ATTN_PREFETCH(0);
    STORE_KV(0);
    if (nch > 1) ATTN_PREFETCH(64);
    __syncthreads();

    for (int c = 0; c < nch; c++) {
        int j0 = c << 6;
        int buf = c & 1;

        if (c + 1 < nch) {
            STORE_KV((c + 1) & 1);
            if (c + 2 < nch) ATTN_PREFETCH((c + 2) << 6);
        }

        // S = Q K^T (warp: m16 x n16, own j-slice)
        float acc_s[2][4];
        #pragma unroll
        for (int nt = 0; nt < 2; nt++)
            #pragma unroll
            for (int r = 0; r < 4; r++) acc_s[nt][r] = 0.f;

        uint32_t ks_base = Ks_u + (uint32_t)((buf * KVBUF) << 1);
        #pragma unroll
        for (int ks = 0; ks < 4; ks++) {
            uint32_t a0, a1, a2, a3;
            ldsm4(a0, a1, a2, a3,
                  Qs_u + (uint32_t)(((m_base + a_row) * PITCH + ks * 16 + a_kof) << 1));
            #pragma unroll
            for (int nt = 0; nt < 2; nt++) {
                uint32_t b0, b1;
                ldsm2(b0, b1,
                      ks_base + (uint32_t)(((n_base + nt * 8 + b_row) * PITCH + ks * 16 + b_kof) << 1));
                mma_f16(acc_s[nt], a0, a1, a2, a3, b0, b1);
            }
        }

        // mask + exp -> packed half2 (A-fragment of PV) + Ps store + rowsum
        int kl0 = n_base + 2 * qcol;
        int kl1 = kl0 + 8;
        int kg0 = j0 + kl0, kg1 = j0 + kl1;
        float e0 = (kg0     <= qg0 && kg0     < kv) ? __expf(acc_s[0][0]) : 0.f;
        float e1 = (kg0 + 1 <= qg0 && kg0 + 1 < kv) ? __expf(acc_s[0][1]) : 0.f;
        float e2 = (kg0     <= qg1 && kg0     < kv) ? __expf(acc_s[0][2]) : 0.f;
        float e3 = (kg0 + 1 <= qg1 && kg0 + 1 < kv) ? __expf(acc_s[0][3]) : 0.f;
        float f0 = (kg1     <= qg0 && kg1     < kv) ? __expf(acc_s[1][0]) : 0.f;
        float f1 = (kg1 + 1 <= qg0 && kg1 + 1 < kv) ? __expf(acc_s[1][1]) : 0.f;
        float f2 = (kg1     <= qg1 && kg1     < kv) ? __expf(acc_s[1][2]) : 0.f;
        float f3 = (kg1 + 1 <= qg1 && kg1 + 1 < kv) ? __expf(acc_s[1][3]) : 0.f;

        __half2 h_pa0 = __floats2half2_rn(e0, e1);
        __half2 h_pa1 = __floats2half2_rn(e2, e3);
        __half2 h_pa2 = __floats2half2_rn(f0, f1);
        __half2 h_pa3 = __floats2half2_rn(f2, f3);
        uint32_t pa0 = *(uint32_t*)&h_pa0;
        uint32_t pa1 = *(uint32_t*)&h_pa1;
        uint32_t pa2 = *(uint32_t*)&h_pa2;
        uint32_t pa3 = *(uint32_t*)&h_pa3;

        *(__half2*)&Ps[(m_base + qrow) * PPITCH + j0 + kl0]     = h_pa0;
        *(__half2*)&Ps[(m_base + qrow + 8) * PPITCH + j0 + kl0] = h_pa1;
        *(__half2*)&Ps[(m_base + qrow) * PPITCH + j0 + kl1]     = h_pa2;
        *(__half2*)&Ps[(m_base + qrow + 8) * PPITCH + j0 + kl1] = h_pa3;

        float s0 = e0 + e1 + f0 + f1;
        float s1 = e2 + e3 + f2 + f3;
        s0 += __shfl_xor_sync(0xffffffffu, s0, 1);
        s0 += __shfl_xor_sync(0xffffffffu, s0, 2);
        s1 += __shfl_xor_sync(0xffffffffu, s1, 1);
        s1 += __shfl_xor_sync(0xffffffffu, s1, 2);
        if (qcol == 0) {
            int nh = (warp & 3) << 6;
            rsA[nh + m_base + qrow]     += s0;
            rsA[nh + m_base + qrow + 8] += s1;
        }

        // PV partial: A = packed exp regs (m16 x k16 over own j-slice),
        // B = V[j-slice][dv], full dv range -> 8 n-tiles.
        uint32_t vs_base = Vs_u + (uint32_t)((buf * KVBUF) << 1);
        #pragma unroll
        for (int dvt = 0; dvt < 8; dvt++) {
            uint32_t b0, b1;
            ldsm2(b0, b1,
                  vs_base + (uint32_t)(((dvt * 8 + b_row) * PITCH + n_base + b_kof) << 1));
            mma_f16(acc_o[dvt], pa0, pa1, pa2, pa3, b0, b1);
        }

        __syncthreads();   // buf[(c+1)&1] stores visible; buf[c&1] free for c+1's store
    }
    #undef ATTN_PREFETCH
    #undef STORE_KV

    // single-pass normalized attn write (+ zero-fill beyond computed cols)
    {
        int cend = nch << 6;
        for (int rr = warp; rr < 64; rr += 16) {
            int q = q0 + rr;
            float inv = 1.0f / (rsA[rr] + rsA[64 + rr] + rsA[128 + rr] + rsA[192 + rr]);
            float* rowp = out_attn + (((size_t)(bh << 10 | q)) << 10);
            const __half* prow = Ps + rr * PPITCH;
            #pragma unroll
            for (int i = 0; i < 8; i++) {
                int col = i * 128 + lane * 4;
                float4 w4;
                if (col < cend) {
                    uint2 uu = *(const uint2*)(prow + col);
                    __half2 h0 = *(__half2*)&uu.x;
                    __half2 h1 = *(__half2*)&uu.y;
                    float2 f0_ = __half22float2(h0);
                    float2 f1_ = __half22float2(h1);
                    w4.x = f0_.x * inv; w4.y = f0_.y * inv;
                    w4.z = f1_.x * inv; w4.w = f1_.y * inv;
                } else {
                    w4 = make_float4(0.f, 0.f, 0.f, 0.f);
                }
                *(float4*)(rowp + col) = w4;
            }
        }
    }
    __syncthreads();   // Ps reads done; Obuf may overwrite

    // O reduction: each warp dumps its partial O (own j-slice) to Obuf[js]
    {
        float* ob = Obuf + (warp & 3) * 4096;
        #pragma unroll
        for (int dvt = 0; dvt < 8; dvt++) {
            int col = dvt * 8 + 2 * qcol;
            *(float2*)&ob[(m_base + qrow) * 64 + col] =
                make_float2(acc_o[dvt][0], acc_o[dvt][1]);
            *(float2*)&ob[(m_base + qrow + 8) * 64 + col] =
                make_float2(acc_o[dvt][2], acc_o[dvt][3]);
        }
    }
    __syncthreads();

    // out_seq epilogue: x + (sum of 4 partials)/rowsum
    {
        for (int cell = tid; cell < 2048; cell += 512) {
            int row = cell >> 5;              // 0..63
            int c2 = (cell & 31) << 1;        // dv pair base
            float2 acc = make_float2(0.f, 0.f);
            #pragma unroll
            for (int js = 0; js < 4; js++) {
                float2 v = *(const float2*)&Obuf[js * 4096 + row * 64 + c2];
                acc.x += v.x;
                acc.y += v.y;
            }
            float inv = 1.0f / (rsA[row] + rsA[64 + row] + rsA[128 + row] + rsA[192 + row]);
            size_t off = (((size_t)(b_ << 10 | (q0 + row))) << 10) + (h << 6) + c2;
            float2 xv = *(const float2*)(x + off);
            float2 o;
            o.x = xv.x + acc.x * inv;
            o.y = xv.y + acc.y * inv;
            *(float2*)(out_seq + off) = o;
        }
    }
}

// ---------------------------------------------------------------------------
extern "C" void kernel_launch(void* const* d_in, const int* in_sizes, int n_in,
                              void* d_out, int out_size) {
    (void)in_sizes; (void)n_in; (void)out_size;
    const float* x     = (const float*)d_in[0];
    const int*   kvlen = (const int*)d_in[3];
    const float* gamma = (const float*)d_in[4];
    const float* beta  = (const float*)d_in[5];
    const float* Wq = (const float*)d_in[6];
    const float* bq = (const float*)d_in[7];
    const float* Wk = (const float*)d_in[8];
    const float* bk = (const float*)d_in[9];
    const float* Wv = (const float*)d_in[10];
    const float* bv = (const float*)d_in[11];

    float* out_seq  = (float*)d_out;
    float* out_attn = out_seq + (size_t)NB * NS * ND;

    ln_kernel<<<NM, 256>>>(x, gamma, beta);
    wt_kernel<<<dim3(32, 32, 3), 256>>>(Wq, Wk, Wv);
    qkv_gemm<<<dim3(8, 32, 3), 256>>>(bq, bk, bv);

    cudaFuncSetAttribute(attn_kernel,
                         cudaFuncAttributeMaxDynamicSharedMemorySize, ATTN_SMEM_B);
    attn_kernel<<<dim3(16, 64), 512, ATTN_SMEM_B>>>(x, kvlen, out_seq, out_attn);
}

// round 16
// speedup vs baseline: 1.0389x; 1.0389x over previous
#include <cuda_runtime.h>
#include <cuda_fp16.h>
#include <cstdint>

// Problem constants
#define NB 4
#define NS 1024
#define ND 1024
#define NH 16
#define DH 64
#define NM (NB * NS)   // 4096 rows

// Scratch (allocation-free rule: __device__ globals)
__device__ __half g_xn[NM * ND];       // layernormed x, fp16, [4096][1024]
__device__ __half g_wt[3 * ND * ND];   // W^T fp16, [z][n][k]
__device__ __half g_qh[NM * ND];       // [B*H][S][64], PRE-SCALED by 0.125
__device__ __half g_kh[NM * ND];
__device__ __half g_vh[NM * ND];

// ---------------------------------------------------------------------------
// helpers
// ---------------------------------------------------------------------------
__device__ __forceinline__ void mma_f16(float c[4],
                                        uint32_t a0, uint32_t a1, uint32_t a2, uint32_t a3,
                                        uint32_t b0, uint32_t b1) {
    asm volatile(
        "mma.sync.aligned.m16n8k16.row.col.f32.f16.f16.f32 "
        "{%0,%1,%2,%3},{%4,%5,%6,%7},{%8,%9},{%0,%1,%2,%3};\n"
        : "+f"(c[0]), "+f"(c[1]), "+f"(c[2]), "+f"(c[3])
        : "r"(a0), "r"(a1), "r"(a2), "r"(a3), "r"(b0), "r"(b1));
}

__device__ __forceinline__ void ldsm4(uint32_t& r0, uint32_t& r1, uint32_t& r2, uint32_t& r3,
                                      uint32_t addr) {
    asm volatile("ldmatrix.sync.aligned.m8n8.x4.shared.b16 {%0,%1,%2,%3}, [%4];"
                 : "=r"(r0), "=r"(r1), "=r"(r2), "=r"(r3) : "r"(addr));
}
__device__ __forceinline__ void ldsm2(uint32_t& r0, uint32_t& r1, uint32_t addr) {
    asm volatile("ldmatrix.sync.aligned.m8n8.x2.shared.b16 {%0,%1}, [%2];"
                 : "=r"(r0), "=r"(r1) : "r"(addr));
}
__device__ __forceinline__ uint32_t smem_u32(const void* p) {
    return (uint32_t)__cvta_generic_to_shared(p);
}

// ---------------------------------------------------------------------------
// Kernel 1: LayerNorm -> fp16. One block per row, 256 threads.
// ---------------------------------------------------------------------------
__global__ void __launch_bounds__(256)
ln_kernel(const float* __restrict__ x,
          const float* __restrict__ gamma,
          const float* __restrict__ beta) {
    int row = blockIdx.x;
    int tid = threadIdx.x;
    const float4* xr = reinterpret_cast<const float4*>(x + (size_t)row * ND);
    float4 v = xr[tid];

    float s1 = v.x + v.y + v.z + v.w;
    float s2 = v.x * v.x + v.y * v.y + v.z * v.z + v.w * v.w;

    __shared__ float red1[8];
    __shared__ float red2[8];
    #pragma unroll
    for (int o = 16; o; o >>= 1) {
        s1 += __shfl_xor_sync(0xffffffffu, s1, o);
        s2 += __shfl_xor_sync(0xffffffffu, s2, o);
    }
    if ((tid & 31) == 0) { red1[tid >> 5] = s1; red2[tid >> 5] = s2; }
    __syncthreads();
    if (tid == 0) {
        float t1 = 0.f, t2 = 0.f;
        #pragma unroll
        for (int i = 0; i < 8; i++) { t1 += red1[i]; t2 += red2[i]; }
        red1[0] = t1; red2[0] = t2;
    }
    __syncthreads();
    float mu = red1[0] * (1.0f / ND);
    float var = red2[0] * (1.0f / ND) - mu * mu;
    float rstd = rsqrtf(var + 1e-5f);

    const float4 g4 = reinterpret_cast<const float4*>(gamma)[tid];
    const float4 b4 = reinterpret_cast<const float4*>(beta)[tid];
    float o0 = (v.x - mu) * rstd * g4.x + b4.x;
    float o1 = (v.y - mu) * rstd * g4.y + b4.y;
    float o2 = (v.z - mu) * rstd * g4.z + b4.z;
    float o3 = (v.w - mu) * rstd * g4.w + b4.w;

    size_t off = (size_t)row * ND + tid * 4;
    *reinterpret_cast<__half2*>(g_xn + off)     = __floats2half2_rn(o0, o1);
    *reinterpret_cast<__half2*>(g_xn + off + 2) = __floats2half2_rn(o2, o3);
}

// ---------------------------------------------------------------------------
// Kernel 1b: W transpose -> fp16. Wt[n][k] = W[k][n].
// ---------------------------------------------------------------------------
__global__ void __launch_bounds__(256)
wt_kernel(const float* __restrict__ Wq, const float* __restrict__ Wk,
          const float* __restrict__ Wv) {
    __shared__ float t[32][33];
    int z = blockIdx.z;
    const float* W = (z == 0) ? Wq : (z == 1) ? Wk : Wv;
    __half* oh = g_wt + (size_t)z * ND * ND;

    int k0 = blockIdx.x << 5, n0 = blockIdx.y << 5;
    int tx = threadIdx.x & 31, ty = threadIdx.x >> 5;

    #pragma unroll
    for (int i = 0; i < 32; i += 8)
        t[ty + i][tx] = W[(size_t)(k0 + ty + i) * ND + n0 + tx];
    __syncthreads();
    #pragma unroll
    for (int i = 0; i < 32; i += 8) {
        int n = ty + i;
        oh[(size_t)(n0 + n) * ND + k0 + tx] = __float2half_rn(t[tx][n]);
    }
}

// ---------------------------------------------------------------------------
// Kernel 2: QKV projection GEMM, fp16 m16n8k16 (unchanged from R8).
// ---------------------------------------------------------------------------
#define PITCH 72

__global__ void __launch_bounds__(256)
qkv_gemm(const float* __restrict__ bq, const float* __restrict__ bk,
         const float* __restrict__ bv) {
    __shared__ __half As[128 * PITCH];
    __shared__ __half Bs[128 * PITCH];

    int z = blockIdx.z;
    const float* bias = (z == 0) ? bq : (z == 1) ? bk : bv;
    __half* outp      = (z == 0) ? g_qh : (z == 1) ? g_kh : g_vh;
    float osc = (z == 0) ? 0.125f : 1.0f;
    const __half* W = g_wt + (size_t)z * ND * ND;

    int tid  = threadIdx.x;
    int lane = tid & 31;
    int warp = tid >> 5;
    int m_base = (warp & 1) * 64;
    int n_base = (warp >> 1) * 32;
    int qrow = lane >> 2;
    int qcol = lane & 3;

    int m0 = blockIdx.y << 7;
    int n0 = blockIdx.x << 7;

    int a_row = (lane & 7) + ((lane >> 3) & 1) * 8;
    int a_kof = ((lane >> 4) & 1) * 8;
    int b_row = lane & 7;
    int b_kof = ((lane >> 3) & 1) * 8;

    uint32_t As_u = smem_u32(As);
    uint32_t Bs_u = smem_u32(Bs);

    float acc[4][4][4];
    #pragma unroll
    for (int mt = 0; mt < 4; mt++)
        #pragma unroll
        for (int nt = 0; nt < 4; nt++)
            #pragma unroll
            for (int r = 0; r < 4; r++) acc[mt][nt][r] = 0.f;

    int r = tid >> 3, u = tid & 7;
    const __half* agp = g_xn + (size_t)(m0 + r) * ND + u * 8;
    const __half* bgp = W + (size_t)(n0 + r) * ND + u * 8;

    uint4 av[4], bv4[4];
    #pragma unroll
    for (int i = 0; i < 4; i++) av[i]  = *(const uint4*)(agp + (size_t)(32 * i) * ND);
    #pragma unroll
    for (int i = 0; i < 4; i++) bv4[i] = *(const uint4*)(bgp + (size_t)(32 * i) * ND);

    for (int it = 0; it < 16; it++) {
        __syncthreads();
        #pragma unroll
        for (int i = 0; i < 4; i++)
            *(uint4*)&As[(r + 32 * i) * PITCH + u * 8] = av[i];
        #pragma unroll
        for (int i = 0; i < 4; i++)
            *(uint4*)&Bs[(r + 32 * i) * PITCH + u * 8] = bv4[i];
        __syncthreads();

        if (it + 1 < 16) {
            int kof = (it + 1) * 64;
            #pragma unroll
            for (int i = 0; i < 4; i++) av[i]  = *(const uint4*)(agp + (size_t)(32 * i) * ND + kof);
            #pragma unroll
            for (int i = 0; i < 4; i++) bv4[i] = *(const uint4*)(bgp + (size_t)(32 * i) * ND + kof);
        }

        #pragma unroll
        for (int ks = 0; ks < 4; ks++) {
            uint32_t af[4][4];
            #pragma unroll
            for (int mt = 0; mt < 4; mt++)
                ldsm4(af[mt][0], af[mt][1], af[mt][2], af[mt][3],
                      As_u + (uint32_t)(((m_base + mt * 16 + a_row) * PITCH + ks * 16 + a_kof) << 1));
            uint32_t bf[4][2];
            #pragma unroll
            for (int nt = 0; nt < 4; nt++)
                ldsm2(bf[nt][0], bf[nt][1],
                      Bs_u + (uint32_t)(((n_base + nt * 8 + b_row) * PITCH + ks * 16 + b_kof) << 1));
            #pragma unroll
            for (int mt = 0; mt < 4; mt++)
                #pragma unroll
                for (int nt = 0; nt < 4; nt++)
                    mma_f16(acc[mt][nt],
                            af[mt][0], af[mt][1], af[mt][2], af[mt][3],
                            bf[nt][0], bf[nt][1]);
        }
    }

    #pragma unroll
    for (int mt = 0; mt < 4; mt++) {
        #pragma unroll
        for (int nt = 0; nt < 4; nt++) {
            int col = n0 + n_base + nt * 8 + 2 * qcol;
            int h = col >> 6, d = col & 63;
            float bx = bias[col], by = bias[col + 1];
            #pragma unroll
            for (int half_ = 0; half_ < 2; half_++) {
                int row = m0 + m_base + mt * 16 + qrow + half_ * 8;
                int b_ = row >> 10, s = row & 1023;
                __half2 hv = __floats2half2_rn((acc[mt][nt][half_ * 2 + 0] + bx) * osc,
                                               (acc[mt][nt][half_ * 2 + 1] + by) * osc);
                *(__half2*)(outp + (size_t)(((b_ * NH + h) << 10) + s) * DH + d) = hv;
            }
        }
    }
}

// ---------------------------------------------------------------------------
// Kernel 3: attention, fp16 mma, single-pass output, 32-ROW q-tiles.
// 256 threads (8 warps, 2x4 grid: m in {0,16}, j/dv slice in {0,16,32,48}).
// R12-proven per-chunk structure (smem P, 3 syncs); smem 90.6 KB -> 2 CTA/SM,
// two independent barrier domains per SM hide sync + dependency stalls.
// ---------------------------------------------------------------------------
#define PPITCH 1048
// smem: Qs 4608 | Ks 9216 | Vs 9216 | rsA 512 | Ps 67072  = 90624
#define ATTN_SMEM_B (4608 + 9216 + 9216 + 512 + 32 * PPITCH * 2)

__global__ void __launch_bounds__(256)
attn_kernel(const float* __restrict__ x,
            const int* __restrict__ kvlen,
            float* __restrict__ out_seq,
            float* __restrict__ out_attn) {
    extern __shared__ char smc[];
    __half* Qs  = (__half*)smc;                         // [32][72]
    __half* Ks  = (__half*)(smc + 4608);                // [64][72]
    __half* Vs  = (__half*)(smc + 13824);               // [dv 64][72]
    float*  rsA = (float*)(smc + 23040);                // [4][32]
    __half* Ps  = (__half*)(smc + 23552);               // [32][PPITCH]

    int tid  = threadIdx.x;
    int lane = tid & 31;
    int warp = tid >> 5;                        // 0..7
    int m_base = (warp >> 2) << 4;              // 0,16
    int n_base = (warp & 3) << 4;               // 0,16,32,48
    int qrow = lane >> 2;
    int qcol = lane & 3;

    int a_row = (lane & 7) + ((lane >> 3) & 1) * 8;
    int a_kof = ((lane >> 4) & 1) * 8;
    int b_row = lane & 7;
    int b_kof = ((lane >> 3) & 1) * 8;

    uint32_t Qs_u = smem_u32(Qs);
    uint32_t Ks_u = smem_u32(Ks);
    uint32_t Vs_u = smem_u32(Vs);
    uint32_t Ps_u = smem_u32(Ps);

    int bh = blockIdx.y;
    int b_ = bh >> 4, h = bh & 15;
    int q0 = (31 - blockIdx.x) << 5;            // heavy blocks first
    int kv = kvlen[b_];

    // load Q tile: one uint4 per thread (32 rows x 8 groups = 256)
    {
        int r = tid >> 3, u = tid & 7;
        *(uint4*)&Qs[r * PITCH + u * 8] =
            *(const uint4*)(g_qh + (size_t)(bh * NS + q0 + r) * DH + u * 8);
    }
    if (tid < 128) rsA[tid] = 0.f;

    float acc_o[2][4];
    #pragma unroll
    for (int nt = 0; nt < 2; nt++)
        #pragma unroll
        for (int r = 0; r < 4; r++) acc_o[nt][r] = 0.f;

    int qg0 = q0 + m_base + qrow;
    int qg1 = qg0 + 8;

    int jend = min(q0 + 32, kv);
    int nch = (jend + 63) >> 6;

    const __half* kb = g_kh + (size_t)(bh * NS) * DH;
    const __half* vb = g_vh + (size_t)(bh * NS) * DH;
    int kr = tid >> 3, ku = tid & 7;            // K: rows kr, kr+32; group 0..7
    int vp = tid >> 3, vu = tid & 7;            // V: row-pair 0..31

    uint4 kreg0, kreg1, vreg0, vreg1;
    #define ATTN_PREFETCH(j0_)                                                   \
        do {                                                                     \
            kreg0 = *(const uint4*)(kb + (size_t)((j0_) + kr) * DH + ku * 8);    \
            kreg1 = *(const uint4*)(kb + (size_t)((j0_) + kr + 32) * DH + ku * 8);\
            vreg0 = *(const uint4*)(vb + (size_t)((j0_) + 2 * vp) * DH + vu * 8);\
            vreg1 = *(const uint4*)(vb + (size_t)((j0_) + 2 * vp + 1) * DH + vu * 8);\
        } while (0)

    ATTN_PREFETCH(0);

    for (int c = 0; c < nch; c++) {
        int j0 = c << 6;
        __syncthreads();   // Ks/Vs free from previous chunk's mma

        *(uint4*)&Ks[kr * PITCH + ku * 8]        = kreg0;
        *(uint4*)&Ks[(kr + 32) * PITCH + ku * 8] = kreg1;
        {
            const uint32_t* pa = (const uint32_t*)&vreg0;
            const uint32_t* pb = (const uint32_t*)&vreg1;
            #pragma unroll
            for (int i = 0; i < 4; i++) {
                uint32_t lo = __byte_perm(pa[i], pb[i], 0x5410);
                uint32_t hi = __byte_perm(pa[i], pb[i], 0x7632);
                int dv = vu * 8 + 2 * i;
                *(uint32_t*)&Vs[dv * PITCH + 2 * vp]       = lo;
                *(uint32_t*)&Vs[(dv + 1) * PITCH + 2 * vp] = hi;
            }
        }
        __syncthreads();

        if (c + 1 < nch) ATTN_PREFETCH((c + 1) << 6);

        // S = Q K^T (warp: m16 x n16, own j-slice)
        float acc_s[2][4];
        #pragma unroll
        for (int nt = 0; nt < 2; nt++)
            #pragma unroll
            for (int r = 0; r < 4; r++) acc_s[nt][r] = 0.f;

        #pragma unroll
        for (int ks = 0; ks < 4; ks++) {
            uint32_t a0, a1, a2, a3;
            ldsm4(a0, a1, a2, a3,
                  Qs_u + (uint32_t)(((m_base + a_row) * PITCH + ks * 16 + a_kof) << 1));
            #pragma unroll
            for (int nt = 0; nt < 2; nt++) {
                uint32_t b0, b1;
                ldsm2(b0, b1,
                      Ks_u + (uint32_t)(((n_base + nt * 8 + b_row) * PITCH + ks * 16 + b_kof) << 1));
                mma_f16(acc_s[nt], a0, a1, a2, a3, b0, b1);
            }
        }

        // mask + exp -> Ps (fp16) ; rowsum from fp32 fragments
        float s0 = 0.f, s1 = 0.f;
        #pragma unroll
        for (int nt = 0; nt < 2; nt++) {
            int kl = n_base + nt * 8 + 2 * qcol;
            int kg = j0 + kl;
            float e0 = (kg     <= qg0 && kg     < kv) ? __expf(acc_s[nt][0]) : 0.f;
            float e1 = (kg + 1 <= qg0 && kg + 1 < kv) ? __expf(acc_s[nt][1]) : 0.f;
            float e2 = (kg     <= qg1 && kg     < kv) ? __expf(acc_s[nt][2]) : 0.f;
            float e3 = (kg + 1 <= qg1 && kg + 1 < kv) ? __expf(acc_s[nt][3]) : 0.f;
            s0 += e0 + e1;
            s1 += e2 + e3;
            *(__half2*)&Ps[(m_base + qrow) * PPITCH + j0 + kl]     = __floats2half2_rn(e0, e1);
            *(__half2*)&Ps[(m_base + qrow + 8) * PPITCH + j0 + kl] = __floats2half2_rn(e2, e3);
        }
        s0 += __shfl_xor_sync(0xffffffffu, s0, 1);
        s0 += __shfl_xor_sync(0xffffffffu, s0, 2);
        s1 += __shfl_xor_sync(0xffffffffu, s1, 1);
        s1 += __shfl_xor_sync(0xffffffffu, s1, 2);
        if (qcol == 0) {
            int nh = (warp & 3) << 5;
            rsA[nh + m_base + qrow]     += s0;
            rsA[nh + m_base + qrow + 8] += s1;
        }
        __syncthreads();   // other warps' P columns visible for PV

        // O += P @ V   (A: Ps rows m_base..+16 over this chunk's 64 j;
        //               B: Vs rows n_base..+16 = dv slice)
        #pragma unroll
        for (int ks = 0; ks < 4; ks++) {
            uint32_t a0, a1, a2, a3;
            ldsm4(a0, a1, a2, a3,
                  Ps_u + (uint32_t)(((m_base + a_row) * PPITCH + j0 + ks * 16 + a_kof) << 1));
            #pragma unroll
            for (int nt = 0; nt < 2; nt++) {
                uint32_t b0, b1;
                ldsm2(b0, b1,
                      Vs_u + (uint32_t)(((n_base + nt * 8 + b_row) * PITCH + ks * 16 + b_kof) << 1));
                mma_f16(acc_o[nt], a0, a1, a2, a3, b0, b1);
            }
        }
    }
    #undef ATTN_PREFETCH
    __syncthreads();

    // single-pass normalized attn write (+ zero-fill beyond computed cols)
    {
        int cend = nch << 6;
        for (int rr = warp; rr < 32; rr += 8) {
            int q = q0 + rr;
            float inv = 1.0f / (rsA[rr] + rsA[32 + rr] + rsA[64 + rr] + rsA[96 + rr]);
            float* rowp = out_attn + (((size_t)(bh << 10 | q)) << 10);
            const __half* prow = Ps + rr * PPITCH;
            #pragma unroll
            for (int i = 0; i < 8; i++) {
                int col = i * 128 + lane * 4;
                float4 w4;
                if (col < cend) {
                    uint2 uu = *(const uint2*)(prow + col);
                    __half2 h0 = *(__half2*)&uu.x;
                    __half2 h1 = *(__half2*)&uu.y;
                    float2 f0 = __half22float2(h0);
                    float2 f1 = __half22float2(h1);
                    w4.x = f0.x * inv; w4.y = f0.y * inv;
                    w4.z = f1.x * inv; w4.w = f1.y * inv;
                } else {
                    w4 = make_float4(0.f, 0.f, 0.f, 0.f);
                }
                *(float4*)(rowp + col) = w4;
            }
        }
    }

    // out_seq epilogue: x + O/rowsum (per warp m16 x dv16 C-fragments)
    {
        int r0i = m_base + qrow, r1i = r0i + 8;
        float inv0 = 1.0f / (rsA[r0i] + rsA[32 + r0i] + rsA[64 + r0i] + rsA[96 + r0i]);
        float inv1 = 1.0f / (rsA[r1i] + rsA[32 + r1i] + rsA[64 + r1i] + rsA[96 + r1i]);
        #pragma unroll
        for (int nt = 0; nt < 2; nt++) {
            int dv = n_base + nt * 8 + 2 * qcol;
            size_t off0 = (((size_t)(b_ << 10 | qg0)) << 10) + (h << 6) + dv;
            size_t off1 = (((size_t)(b_ << 10 | qg1)) << 10) + (h << 6) + dv;
            float2 x0 = *(const float2*)(x + off0);
            float2 x1 = *(const float2*)(x + off1);
            float2 o0, o1;
            o0.x = x0.x + acc_o[nt][0] * inv0;
            o0.y = x0.y + acc_o[nt][1] * inv0;
            o1.x = x1.x + acc_o[nt][2] * inv1;
            o1.y = x1.y + acc_o[nt][3] * inv1;
            *(float2*)(out_seq + off0) = o0;
            *(float2*)(out_seq + off1) = o1;
        }
    }
}

// ---------------------------------------------------------------------------
extern "C" void kernel_launch(void* const* d_in, const int* in_sizes, int n_in,
                              void* d_out, int out_size) {
    (void)in_sizes; (void)n_in; (void)out_size;
    const float* x     = (const float*)d_in[0];
    const int*   kvlen = (const int*)d_in[3];
    const float* gamma = (const float*)d_in[4];
    const float* beta  = (const float*)d_in[5];
    const float* Wq = (const float*)d_in[6];
    const float* bq = (const float*)d_in[7];
    const float* Wk = (const float*)d_in[8];
    const float* bk = (const float*)d_in[9];
    const float* Wv = (const float*)d_in[10];
    const float* bv = (const float*)d_in[11];

    float* out_seq  = (float*)d_out;
    float* out_attn = out_seq + (size_t)NB * NS * ND;

    ln_kernel<<<NM, 256>>>(x, gamma, beta);
    wt_kernel<<<dim3(32, 32, 3), 256>>>(Wq, Wk, Wv);
    qkv_gemm<<<dim3(8, 32, 3), 256>>>(bq, bk, bv);

    cudaFuncSetAttribute(attn_kernel,
                         cudaFuncAttributeMaxDynamicSharedMemorySize, ATTN_SMEM_B);
    attn_kernel<<<dim3(32, 64), 256, ATTN_SMEM_B>>>(x, kvlen, out_seq, out_attn);
}